// round 6
// baseline (speedup 1.0000x reference)
#include <cuda_runtime.h>
#include <cuda_fp16.h>
#include <cstdint>

// ============================================================================
// CompressedLinear: out[M,N] = x[M,K] @ (W[N,K] * scale[n])^T + bias[n]
// M=2048, N=11008, K=4096.
// KEY: the harness materializes weight_int8 as INT32 (int8 unsupported in the
// harness dtype set; rel_err 1.11801 = sqrt(1.25) signature proved it).
// Base-sm_100 target: mma.sync.m16n8k16 f32.f16.f16.f32, CTA tile 128x128,
// KC=64, 4-stage cp.async pipeline. A = fp16 x (pre-converted), B = int32 W
// -> low-byte gather -> fp16 dequant in registers -> swizzled STS.
// ============================================================================

#define MT 128
#define NT 128
#define KC 64
#define STAGES 4
#define M_TOTAL 2048
#define N_TOTAL 11008
#define K_TOTAL 4096
#define NKC (K_TOTAL / KC)           // 64
#define M_TILES (M_TOTAL / MT)       // 16
#define N_TILES (N_TOTAL / NT)       // 86
#define A_ST (MT * KC * 2)           // 16384
#define B_ST (NT * KC * 2)           // 16384
#define STAGE_BYTES (A_ST + B_ST)    // 32768
#define SMEM_BYTES (STAGES * STAGE_BYTES)  // 131072

// fp16 copy of x, written by convert kernel, read by GEMM kernel (16 MB).
// 256B alignment: cp.async reads 16B chunks from this buffer.
__device__ __align__(256) __half g_x_half[(size_t)M_TOTAL * K_TOTAL];

#define SWZ(o) ((o) ^ (((o) >> 3) & 0x70))

// ---------------------------------------------------------------------------
// primitive wrappers (base sm_100 legal)
// ---------------------------------------------------------------------------
static __device__ __forceinline__ void cp16(uint32_t dst, const void* src) {
    asm volatile("cp.async.cg.shared.global [%0], [%1], 16;"
                 :: "r"(dst), "l"(src) : "memory");
}

static __device__ __forceinline__ void sts128(uint32_t addr, uint4 v) {
    asm volatile("st.shared.v4.b32 [%0], {%1, %2, %3, %4};"
                 :: "r"(addr), "r"(v.x), "r"(v.y), "r"(v.z), "r"(v.w)
                 : "memory");
}

static __device__ __forceinline__ void ldsm4(uint32_t r[4], uint32_t addr) {
    asm volatile("ldmatrix.sync.aligned.m8n8.x4.shared.b16 {%0,%1,%2,%3}, [%4];"
                 : "=r"(r[0]), "=r"(r[1]), "=r"(r[2]), "=r"(r[3])
                 : "r"(addr));
}

static __device__ __forceinline__ void mma16816(float c[4], const uint32_t a[4],
                                                uint32_t b0, uint32_t b1) {
    asm volatile(
        "mma.sync.aligned.m16n8k16.row.col.f32.f16.f16.f32 "
        "{%0,%1,%2,%3}, {%4,%5,%6,%7}, {%8,%9}, {%0,%1,%2,%3};"
        : "+f"(c[0]), "+f"(c[1]), "+f"(c[2]), "+f"(c[3])
        : "r"(a[0]), "r"(a[1]), "r"(a[2]), "r"(a[3]), "r"(b0), "r"(b1));
}

// Gather the low byte of each of 4 int32s into one packed word.
// For values in [-127,127] the low byte IS the exact int8 two's complement.
static __device__ __forceinline__ uint32_t lb4(uint4 u) {
    uint32_t t0 = __byte_perm(u.x, u.y, 0x0040);   // [x.b0, y.b0, -, -]
    uint32_t t1 = __byte_perm(u.z, u.w, 0x0040);   // [z.b0, w.b0, -, -]
    return __byte_perm(t0, t1, 0x5410);            // [x.b0, y.b0, z.b0, w.b0]
}

// int8 pair -> fp16 pair: bytes pre-XORed with 0x80 (bias +128); PRMT packs
// [b, 0x64] per half => fp16 bits 0x6400+u = 1024+(b+128); subtract 1152
// (0x6480) to recover b exactly (integers, exact in fp16).
static __device__ __forceinline__ uint32_t dq2(uint32_t xw, uint32_t sel) {
    uint32_t p = __byte_perm(xw, 0x64646464u, sel);
    uint32_t r;
    asm("sub.rn.f16x2 %0, %1, %2;" : "=r"(r) : "r"(p), "r"(0x64806480u));
    return r;
}

// ---------------------------------------------------------------------------
// x: f32 -> fp16 pre-pass
// ---------------------------------------------------------------------------
__global__ void __launch_bounds__(256) convert_x_kernel(const float* __restrict__ x) {
    const uint32_t t = blockIdx.x * 256u + threadIdx.x;   // 0 .. 524287
    const float4* xv = reinterpret_cast<const float4*>(x);
    uint2* ov = reinterpret_cast<uint2*>(g_x_half);
    #pragma unroll
    for (int j = 0; j < 4; j++) {
        size_t idx = (size_t)t + (size_t)j * (2048u * 256u);
        float4 v = __ldg(xv + idx);
        __half2 a = __floats2half2_rn(v.x, v.y);
        __half2 b = __floats2half2_rn(v.z, v.w);
        uint2 o;
        o.x = *reinterpret_cast<uint32_t*>(&a);
        o.y = *reinterpret_cast<uint32_t*>(&b);
        ov[idx] = o;
    }
}

// ---------------------------------------------------------------------------
// Main GEMM kernel
// ---------------------------------------------------------------------------
__global__ void __launch_bounds__(256, 1) cl_gemm_kernel(
    const int* __restrict__ W, const float* __restrict__ scale,
    const float* __restrict__ bias, float* __restrict__ out)
{
    extern __shared__ char smem_raw[];
    const uint32_t sbase = (uint32_t)__cvta_generic_to_shared(smem_raw);

    const int tid  = threadIdx.x;
    const int wid  = tid >> 5;
    const int lane = tid & 31;
    // M fastest: consecutive CTAs share the weight panel (L2 reuse); the
    // 16MB fp16 x stays L2-resident across the whole run.
    const int m0 = (int)(blockIdx.x % M_TILES) * MT;
    const int n0 = (int)(blockIdx.x / M_TILES) * NT;

    const int wm = (wid & 1) * 64;   // warp M offset (2 warps in M)
    const int wn = (wid >> 1) * 32;  // warp N offset (4 warps in N)

    // --- load-index precompute ---
    const int a_row = tid >> 3, a_col = tid & 7;   // A: 128B rows, 8x16B chunks
    const int b_row = tid >> 1, b_half = tid & 1;  // B: 128 rows, 2 k-halves (32 int32)
    const char* a_src0 =
        (const char*)(g_x_half + (size_t)(m0 + a_row) * K_TOTAL) + a_col * 16;
    const uint4* b_src0 =
        reinterpret_cast<const uint4*>(W + (size_t)(n0 + b_row) * K_TOTAL) + b_half * 8;
    const uint32_t a_dst0 = SWZ((uint32_t)(a_row * 128 + a_col * 16));
    const uint32_t b_dst0 = (uint32_t)(b_row * 128 + b_half * 64);

    // A cp.async for K-chunk `ls` into stage buffer base aB
    auto load_A = [&](int ls, uint32_t aB) {
        const char* src = a_src0 + (size_t)ls * (KC * 2);
        uint32_t dst = aB + a_dst0;
        #pragma unroll
        for (int i = 0; i < 4; i++)   // rows +32 each: swizzle bits unchanged
            cp16(dst + i * 4096, src + (size_t)i * 32 * K_TOTAL * 2);
    };
    // B global loads (int32 weights) for K-chunk `ls`: 32 consecutive int32
    auto ldg_B = [&](int ls, uint4 v[8]) {
        const uint4* s = b_src0 + (size_t)ls * (KC / 4);   // 64 int32 = 16 uint4 per chunk-row
        #pragma unroll
        for (int j = 0; j < 8; j++) v[j] = __ldg(s + j);
    };
    // low-byte gather + dequant + swizzled store into stage B region bB
    auto sts_B = [&](const uint4 v[8], uint32_t bB) {
        #pragma unroll
        for (int p = 0; p < 4; p++) {           // 2 uint4 (8 int32) -> 16B halfs
            uint32_t w0 = lb4(v[2 * p])     ^ 0x80808080u;
            uint32_t w1 = lb4(v[2 * p + 1]) ^ 0x80808080u;
            uint4 o;
            o.x = dq2(w0, 0x4140); o.y = dq2(w0, 0x4342);
            o.z = dq2(w1, 0x4140); o.w = dq2(w1, 0x4342);
            sts128(bB + SWZ(b_dst0 + (uint32_t)p * 16u), o);
        }
    };

    // --- prologue: fill STAGES-1 stages ---
    #pragma unroll
    for (int i = 0; i < STAGES - 1; i++) {
        uint32_t aB = sbase + (uint32_t)i * STAGE_BYTES;
        uint4 v[8];
        ldg_B(i, v);
        load_A(i, aB);
        sts_B(v, aB + A_ST);
        asm volatile("cp.async.commit_group;" ::: "memory");
    }

    float acc[4][4][4];
    #pragma unroll
    for (int mi = 0; mi < 4; mi++)
        #pragma unroll
        for (int ni = 0; ni < 4; ni++)
            #pragma unroll
            for (int q = 0; q < 4; q++) acc[mi][ni][q] = 0.f;

    // --- mainloop ---
    #pragma unroll 1
    for (int kc = 0; kc < NKC; kc++) {
        const int ls = kc + STAGES - 1;
        uint4 vb[8];
        if (ls < NKC) ldg_B(ls, vb);

        asm volatile("cp.async.wait_group 2;" ::: "memory");
        __syncthreads();

        const uint32_t lsB = sbase + (uint32_t)(ls & (STAGES - 1)) * STAGE_BYTES;
        if (ls < NKC) load_A(ls, lsB);

        // compute stage kc
        {
            const uint32_t aB = sbase + (uint32_t)(kc & (STAGES - 1)) * STAGE_BYTES;
            const uint32_t bB = aB + A_ST;
            const int lrow = lane & 15;
            const int lk   = (lane >> 4) * 16;
            #pragma unroll
            for (int ks = 0; ks < 4; ks++) {
                const int kb = ks * 32 + lk;
                uint32_t a[4][4], b[2][4];
                #pragma unroll
                for (int mi = 0; mi < 4; mi++)
                    ldsm4(a[mi], aB + SWZ((uint32_t)((wm + mi * 16 + lrow) * 128 + kb)));
                #pragma unroll
                for (int nx = 0; nx < 2; nx++)
                    ldsm4(b[nx], bB + SWZ((uint32_t)((wn + nx * 16 + lrow) * 128 + kb)));
                #pragma unroll
                for (int mi = 0; mi < 4; mi++)
                    #pragma unroll
                    for (int ni = 0; ni < 4; ni++)
                        mma16816(acc[mi][ni], a[mi],
                                 b[ni >> 1][ni & 1], b[ni >> 1][(ni & 1) + 2]);
            }
        }

        if (ls < NKC) sts_B(vb, lsB + A_ST);
        asm volatile("cp.async.commit_group;" ::: "memory");
    }
    asm volatile("cp.async.wait_group 0;" ::: "memory");

    // --- epilogue: scale/bias in registers, direct f32 stores ---
    {
        const int r_base = m0 + wm + (lane >> 2);
        const int c_base = n0 + wn + (lane & 3) * 2;
        #pragma unroll
        for (int ni = 0; ni < 4; ni++) {
            const int c = c_base + ni * 8;
            const float s0 = __ldg(scale + c), s1 = __ldg(scale + c + 1);
            const float g0 = __ldg(bias + c),  g1 = __ldg(bias + c + 1);
            #pragma unroll
            for (int mi = 0; mi < 4; mi++) {
                const int r0 = r_base + mi * 16;
                float2 o;
                o.x = fmaf(acc[mi][ni][0], s0, g0);
                o.y = fmaf(acc[mi][ni][1], s1, g1);
                *reinterpret_cast<float2*>(out + (size_t)r0 * N_TOTAL + c) = o;
                o.x = fmaf(acc[mi][ni][2], s0, g0);
                o.y = fmaf(acc[mi][ni][3], s1, g1);
                *reinterpret_cast<float2*>(out + (size_t)(r0 + 8) * N_TOTAL + c) = o;
            }
        }
    }
}

// ---------------------------------------------------------------------------
// launch
// ---------------------------------------------------------------------------
extern "C" void kernel_launch(void* const* d_in, const int* in_sizes, int n_in,
                              void* d_out, int out_size) {
    (void)in_sizes; (void)n_in; (void)out_size;
    const float* x     = (const float*)d_in[0];
    const int*   w     = (const int*)d_in[1];     // weight_int8 materialized as int32!
    const float* scale = (const float*)d_in[2];
    const float* bias  = (const float*)d_in[3];
    float* out = (float*)d_out;

    cudaFuncSetAttribute(cl_gemm_kernel,
                         cudaFuncAttributeMaxDynamicSharedMemorySize, SMEM_BYTES);

    convert_x_kernel<<<2048, 256>>>(x);
    cl_gemm_kernel<<<M_TILES * N_TILES, 256, SMEM_BYTES>>>(w, scale, bias, out);
}

// round 7
// speedup vs baseline: 1.5656x; 1.5656x over previous
#include <cuda_runtime.h>
#include <cuda_fp16.h>
#include <cstdint>

// ============================================================================
// CompressedLinear: out[M,N] = x[M,K] @ (W[N,K] * scale[n])^T + bias[n]
// M=2048, N=11008, K=4096.  Weights arrive as INT32 (harness dtype set).
// R6 profile: L1tex-bound (71%), tensor 24%.  =>
//   (a) pre-pass dequants W int32->fp16 once into a device buffer; the GEMM
//       mainloop then feeds BOTH operands via cp.async (no LDG/PRMT/STS),
//   (b) CTA tile widened to 128x256 (warp tile 64x64) halving per-output
//       LDSM traffic.
// mma.sync.m16n8k16 f32.f16.f16.f32, KC=64, 4-stage cp.async pipeline.
// ============================================================================

#define MT 128
#define NT 256
#define KC 64
#define STAGES 4
#define M_TOTAL 2048
#define N_TOTAL 11008
#define K_TOTAL 4096
#define NKC (K_TOTAL / KC)           // 64
#define M_TILES (M_TOTAL / MT)       // 16
#define N_TILES (N_TOTAL / NT)       // 43
#define A_ST (MT * KC * 2)           // 16384
#define B_ST (NT * KC * 2)           // 32768
#define STAGE_BYTES (A_ST + B_ST)    // 49152
#define SMEM_BYTES (STAGES * STAGE_BYTES)  // 196608

// fp16 copies built by pre-pass kernels (16 MB + 90 MB), 256B-aligned for cp.async.
__device__ __align__(256) __half g_x_half[(size_t)M_TOTAL * K_TOTAL];
__device__ __align__(256) __half g_w_half[(size_t)N_TOTAL * K_TOTAL];

#define SWZ(o) ((o) ^ (((o) >> 3) & 0x70))

// ---------------------------------------------------------------------------
// primitive wrappers (base sm_100 legal)
// ---------------------------------------------------------------------------
static __device__ __forceinline__ void cp16(uint32_t dst, const void* src) {
    asm volatile("cp.async.cg.shared.global [%0], [%1], 16;"
                 :: "r"(dst), "l"(src) : "memory");
}

static __device__ __forceinline__ void ldsm4(uint32_t r[4], uint32_t addr) {
    asm volatile("ldmatrix.sync.aligned.m8n8.x4.shared.b16 {%0,%1,%2,%3}, [%4];"
                 : "=r"(r[0]), "=r"(r[1]), "=r"(r[2]), "=r"(r[3])
                 : "r"(addr));
}

static __device__ __forceinline__ void mma16816(float c[4], const uint32_t a[4],
                                                uint32_t b0, uint32_t b1) {
    asm volatile(
        "mma.sync.aligned.m16n8k16.row.col.f32.f16.f16.f32 "
        "{%0,%1,%2,%3}, {%4,%5,%6,%7}, {%8,%9}, {%0,%1,%2,%3};"
        : "+f"(c[0]), "+f"(c[1]), "+f"(c[2]), "+f"(c[3])
        : "r"(a[0]), "r"(a[1]), "r"(a[2]), "r"(a[3]), "r"(b0), "r"(b1));
}

// Gather the low byte of each of 4 int32s (exact int8 two's complement).
static __device__ __forceinline__ uint32_t lb4(uint4 u) {
    uint32_t t0 = __byte_perm(u.x, u.y, 0x0040);
    uint32_t t1 = __byte_perm(u.z, u.w, 0x0040);
    return __byte_perm(t0, t1, 0x5410);
}

// int8 pair -> fp16 pair (exact): PRMT pack with 0x64, subtract 1152.
static __device__ __forceinline__ uint32_t dq2(uint32_t xw, uint32_t sel) {
    uint32_t p = __byte_perm(xw, 0x64646464u, sel);
    uint32_t r;
    asm("sub.rn.f16x2 %0, %1, %2;" : "=r"(r) : "r"(p), "r"(0x64806480u));
    return r;
}

// ---------------------------------------------------------------------------
// pre-pass 1: x f32 -> fp16
// ---------------------------------------------------------------------------
__global__ void __launch_bounds__(256) convert_x_kernel(const float* __restrict__ x) {
    const uint32_t t = blockIdx.x * 256u + threadIdx.x;   // 0 .. 524287
    const float4* xv = reinterpret_cast<const float4*>(x);
    uint2* ov = reinterpret_cast<uint2*>(g_x_half);
    #pragma unroll
    for (int j = 0; j < 4; j++) {
        size_t idx = (size_t)t + (size_t)j * (2048u * 256u);
        float4 v = __ldg(xv + idx);
        __half2 a = __floats2half2_rn(v.x, v.y);
        __half2 b = __floats2half2_rn(v.z, v.w);
        uint2 o;
        o.x = *reinterpret_cast<uint32_t*>(&a);
        o.y = *reinterpret_cast<uint32_t*>(&b);
        ov[idx] = o;
    }
}

// ---------------------------------------------------------------------------
// pre-pass 2: W int32 -> fp16 (45,088,768 elements; 8 per thread)
// ---------------------------------------------------------------------------
__global__ void __launch_bounds__(256) convert_w_kernel(const int* __restrict__ W) {
    const size_t t = (size_t)blockIdx.x * 256u + threadIdx.x;  // 0 .. 5636095
    const uint4* wv = reinterpret_cast<const uint4*>(W);
    uint4 u0 = __ldg(wv + 2 * t);
    uint4 u1 = __ldg(wv + 2 * t + 1);
    uint32_t w0 = lb4(u0) ^ 0x80808080u;
    uint32_t w1 = lb4(u1) ^ 0x80808080u;
    uint4 o;
    o.x = dq2(w0, 0x4140); o.y = dq2(w0, 0x4342);
    o.z = dq2(w1, 0x4140); o.w = dq2(w1, 0x4342);
    reinterpret_cast<uint4*>(g_w_half)[t] = o;
}

// ---------------------------------------------------------------------------
// Main GEMM kernel
// ---------------------------------------------------------------------------
__global__ void __launch_bounds__(256, 1) cl_gemm_kernel(
    const float* __restrict__ scale, const float* __restrict__ bias,
    float* __restrict__ out)
{
    extern __shared__ char smem_raw[];
    const uint32_t sbase = (uint32_t)__cvta_generic_to_shared(smem_raw);

    const int tid  = threadIdx.x;
    const int wid  = tid >> 5;
    const int lane = tid & 31;
    // M fastest: consecutive CTAs share the weight panel (L2 reuse); the
    // 16MB fp16 x stays L2-resident across the whole run.
    const int m0 = (int)(blockIdx.x % M_TILES) * MT;
    const int n0 = (int)(blockIdx.x / M_TILES) * NT;

    const int wm = (wid & 1) * 64;   // warp M offset (2 warps in M)
    const int wn = (wid >> 1) * 64;  // warp N offset (4 warps in N, 64 each)

    // --- load-index precompute ---
    const int a_row = tid >> 3, a_col = tid & 7;   // A: 128 rows x 128B, 8x16B chunks
    const int b_row = tid;                          // B: 256 rows x 128B, 1 row/thread
    const char* a_src0 =
        (const char*)(g_x_half + (size_t)(m0 + a_row) * K_TOTAL) + a_col * 16;
    const char* b_src0 =
        (const char*)(g_w_half + (size_t)(n0 + b_row) * K_TOTAL);
    const uint32_t a_dst0 = SWZ((uint32_t)(a_row * 128 + a_col * 16));

    // A cp.async for K-chunk `ls` into stage buffer base aB
    auto load_A = [&](int ls, uint32_t aB) {
        const char* src = a_src0 + (size_t)ls * (KC * 2);
        uint32_t dst = aB + a_dst0;
        #pragma unroll
        for (int i = 0; i < 4; i++)   // rows +32 each: swizzle bits unchanged
            cp16(dst + i * 4096, src + (size_t)i * 32 * K_TOTAL * 2);
    };
    // B cp.async for K-chunk `ls` into stage B region base bB (one row/thread)
    auto load_B = [&](int ls, uint32_t bB) {
        const char* src = b_src0 + (size_t)ls * (KC * 2);
        #pragma unroll
        for (int i = 0; i < 8; i++)
            cp16(bB + SWZ((uint32_t)(b_row * 128 + i * 16)), src + i * 16);
    };

    // --- prologue: fill STAGES-1 stages ---
    #pragma unroll
    for (int i = 0; i < STAGES - 1; i++) {
        uint32_t aB = sbase + (uint32_t)i * STAGE_BYTES;
        load_A(i, aB);
        load_B(i, aB + A_ST);
        asm volatile("cp.async.commit_group;" ::: "memory");
    }

    float acc[4][8][4];
    #pragma unroll
    for (int mi = 0; mi < 4; mi++)
        #pragma unroll
        for (int ni = 0; ni < 8; ni++)
            #pragma unroll
            for (int q = 0; q < 4; q++) acc[mi][ni][q] = 0.f;

    // --- mainloop ---
    #pragma unroll 1
    for (int kc = 0; kc < NKC; kc++) {
        const int ls = kc + STAGES - 1;

        asm volatile("cp.async.wait_group 2;" ::: "memory");
        __syncthreads();

        const uint32_t lsB = sbase + (uint32_t)(ls & (STAGES - 1)) * STAGE_BYTES;
        if (ls < NKC) {
            load_A(ls, lsB);
            load_B(ls, lsB + A_ST);
        }
        asm volatile("cp.async.commit_group;" ::: "memory");

        // compute stage kc
        {
            const uint32_t aB = sbase + (uint32_t)(kc & (STAGES - 1)) * STAGE_BYTES;
            const uint32_t bB = aB + A_ST;
            const int lrow = lane & 15;
            const int lk   = (lane >> 4) * 16;
            #pragma unroll
            for (int ks = 0; ks < 4; ks++) {
                const int kb = ks * 32 + lk;
                uint32_t a[4][4], b[4][4];
                #pragma unroll
                for (int mi = 0; mi < 4; mi++)
                    ldsm4(a[mi], aB + SWZ((uint32_t)((wm + mi * 16 + lrow) * 128 + kb)));
                #pragma unroll
                for (int nx = 0; nx < 4; nx++)
                    ldsm4(b[nx], bB + SWZ((uint32_t)((wn + nx * 16 + lrow) * 128 + kb)));
                #pragma unroll
                for (int mi = 0; mi < 4; mi++)
                    #pragma unroll
                    for (int ni = 0; ni < 8; ni++)
                        mma16816(acc[mi][ni], a[mi],
                                 b[ni >> 1][ni & 1], b[ni >> 1][(ni & 1) + 2]);
            }
        }
    }
    asm volatile("cp.async.wait_group 0;" ::: "memory");

    // --- epilogue: scale/bias in registers, direct f32 stores ---
    {
        const int r_base = m0 + wm + (lane >> 2);
        const int c_base = n0 + wn + (lane & 3) * 2;
        #pragma unroll
        for (int ni = 0; ni < 8; ni++) {
            const int c = c_base + ni * 8;
            const float s0 = __ldg(scale + c), s1 = __ldg(scale + c + 1);
            const float g0 = __ldg(bias + c),  g1 = __ldg(bias + c + 1);
            #pragma unroll
            for (int mi = 0; mi < 4; mi++) {
                const int r0 = r_base + mi * 16;
                float2 o;
                o.x = fmaf(acc[mi][ni][0], s0, g0);
                o.y = fmaf(acc[mi][ni][1], s1, g1);
                *reinterpret_cast<float2*>(out + (size_t)r0 * N_TOTAL + c) = o;
                o.x = fmaf(acc[mi][ni][2], s0, g0);
                o.y = fmaf(acc[mi][ni][3], s1, g1);
                *reinterpret_cast<float2*>(out + (size_t)(r0 + 8) * N_TOTAL + c) = o;
            }
        }
    }
}

// ---------------------------------------------------------------------------
// launch
// ---------------------------------------------------------------------------
extern "C" void kernel_launch(void* const* d_in, const int* in_sizes, int n_in,
                              void* d_out, int out_size) {
    (void)in_sizes; (void)n_in; (void)out_size;
    const float* x     = (const float*)d_in[0];
    const int*   w     = (const int*)d_in[1];     // weight_int8 materialized as int32
    const float* scale = (const float*)d_in[2];
    const float* bias  = (const float*)d_in[3];
    float* out = (float*)d_out;

    cudaFuncSetAttribute(cl_gemm_kernel,
                         cudaFuncAttributeMaxDynamicSharedMemorySize, SMEM_BYTES);

    convert_x_kernel<<<2048, 256>>>(x);
    convert_w_kernel<<<22016, 256>>>(w);
    cl_gemm_kernel<<<M_TILES * N_TILES, 256, SMEM_BYTES>>>(scale, bias, out);
}

// round 10
// speedup vs baseline: 1.7033x; 1.0879x over previous
#include <cuda_runtime.h>
#include <cuda_fp16.h>
#include <cstdint>

// ============================================================================
// CompressedLinear: out[M,N] = x[M,K] @ (W[N,K] * scale[n])^T + bias[n]
// M=2048, N=11008, K=4096.  Weights arrive as INT32 (harness dtype quirk).
// R7: 881us, occ 12.5% (1 CTA/SM).  This round: CTA tile 64x128 (warp 32x32),
// KC=64, STAGES=4 -> 96KB smem/CTA so 2 CTAs/SM fit.  NOTE: no min-blocks in
// __launch_bounds__ — the (256,2) variant crashed the build container 4x in
// a row (suspected ptxas blowup under the min-blocks register constraint);
// register usage is naturally ~100 here so 2 CTAs/SM should still happen.
// mma.sync.m16n8k16 f32.f16.f16.f32; both operands cp.async from fp16
// device buffers built by two pre-pass kernels.
// ============================================================================

#define MT 64
#define NT 128
#define KC 64
#define STAGES 4
#define M_TOTAL 2048
#define N_TOTAL 11008
#define K_TOTAL 4096
#define NKC (K_TOTAL / KC)           // 64
#define M_TILES (M_TOTAL / MT)       // 32
#define N_TILES (N_TOTAL / NT)       // 86
#define A_ST (MT * KC * 2)           // 8192
#define B_ST (NT * KC * 2)           // 16384
#define STAGE_BYTES (A_ST + B_ST)    // 24576
#define SMEM_BYTES (STAGES * STAGE_BYTES)  // 98304

// fp16 copies built by pre-pass kernels (16 MB + 90 MB), 256B-aligned for cp.async.
__device__ __align__(256) __half g_x_half[(size_t)M_TOTAL * K_TOTAL];
__device__ __align__(256) __half g_w_half[(size_t)N_TOTAL * K_TOTAL];

#define SWZ(o) ((o) ^ (((o) >> 3) & 0x70))

// ---------------------------------------------------------------------------
// primitive wrappers (base sm_100 legal)
// ---------------------------------------------------------------------------
static __device__ __forceinline__ void cp16(uint32_t dst, const void* src) {
    asm volatile("cp.async.cg.shared.global [%0], [%1], 16;"
                 :: "r"(dst), "l"(src) : "memory");
}

static __device__ __forceinline__ void ldsm4(uint32_t r[4], uint32_t addr) {
    asm volatile("ldmatrix.sync.aligned.m8n8.x4.shared.b16 {%0,%1,%2,%3}, [%4];"
                 : "=r"(r[0]), "=r"(r[1]), "=r"(r[2]), "=r"(r[3])
                 : "r"(addr));
}

static __device__ __forceinline__ void mma16816(float c[4], const uint32_t a[4],
                                                uint32_t b0, uint32_t b1) {
    asm volatile(
        "mma.sync.aligned.m16n8k16.row.col.f32.f16.f16.f32 "
        "{%0,%1,%2,%3}, {%4,%5,%6,%7}, {%8,%9}, {%0,%1,%2,%3};"
        : "+f"(c[0]), "+f"(c[1]), "+f"(c[2]), "+f"(c[3])
        : "r"(a[0]), "r"(a[1]), "r"(a[2]), "r"(a[3]), "r"(b0), "r"(b1));
}

// Gather the low byte of each of 4 int32s (exact int8 two's complement).
static __device__ __forceinline__ uint32_t lb4(uint4 u) {
    uint32_t t0 = __byte_perm(u.x, u.y, 0x0040);
    uint32_t t1 = __byte_perm(u.z, u.w, 0x0040);
    return __byte_perm(t0, t1, 0x5410);
}

// int8 pair -> fp16 pair (exact): PRMT pack with 0x64, subtract 1152.
static __device__ __forceinline__ uint32_t dq2(uint32_t xw, uint32_t sel) {
    uint32_t p = __byte_perm(xw, 0x64646464u, sel);
    uint32_t r;
    asm("sub.rn.f16x2 %0, %1, %2;" : "=r"(r) : "r"(p), "r"(0x64806480u));
    return r;
}

// ---------------------------------------------------------------------------
// pre-pass 1: x f32 -> fp16
// ---------------------------------------------------------------------------
__global__ void __launch_bounds__(256) convert_x_kernel(const float* __restrict__ x) {
    const uint32_t t = blockIdx.x * 256u + threadIdx.x;   // 0 .. 524287
    const float4* xv = reinterpret_cast<const float4*>(x);
    uint2* ov = reinterpret_cast<uint2*>(g_x_half);
    #pragma unroll
    for (int j = 0; j < 4; j++) {
        size_t idx = (size_t)t + (size_t)j * (2048u * 256u);
        float4 v = __ldg(xv + idx);
        __half2 a = __floats2half2_rn(v.x, v.y);
        __half2 b = __floats2half2_rn(v.z, v.w);
        uint2 o;
        o.x = *reinterpret_cast<uint32_t*>(&a);
        o.y = *reinterpret_cast<uint32_t*>(&b);
        ov[idx] = o;
    }
}

// ---------------------------------------------------------------------------
// pre-pass 2: W int32 -> fp16 (45,088,768 elements; 8 per thread)
// ---------------------------------------------------------------------------
__global__ void __launch_bounds__(256) convert_w_kernel(const int* __restrict__ W) {
    const size_t t = (size_t)blockIdx.x * 256u + threadIdx.x;  // 0 .. 5636095
    const uint4* wv = reinterpret_cast<const uint4*>(W);
    uint4 u0 = __ldg(wv + 2 * t);
    uint4 u1 = __ldg(wv + 2 * t + 1);
    uint32_t w0 = lb4(u0) ^ 0x80808080u;
    uint32_t w1 = lb4(u1) ^ 0x80808080u;
    uint4 o;
    o.x = dq2(w0, 0x4140); o.y = dq2(w0, 0x4342);
    o.z = dq2(w1, 0x4140); o.w = dq2(w1, 0x4342);
    reinterpret_cast<uint4*>(g_w_half)[t] = o;
}

// ---------------------------------------------------------------------------
// Main GEMM kernel: CTA 64x128, warp 32x32, 96KB smem (2 CTAs/SM by resources)
// ---------------------------------------------------------------------------
__global__ void __launch_bounds__(256) cl_gemm_kernel(
    const float* __restrict__ scale, const float* __restrict__ bias,
    float* __restrict__ out)
{
    extern __shared__ char smem_raw[];
    const uint32_t sbase = (uint32_t)__cvta_generic_to_shared(smem_raw);

    const int tid  = threadIdx.x;
    const int wid  = tid >> 5;
    const int lane = tid & 31;
    // M fastest: x (16MB fp16) stays L2-resident; each B panel is shared by
    // 32 consecutive CTAs via L2.
    const int m0 = (int)(blockIdx.x % M_TILES) * MT;
    const int n0 = (int)(blockIdx.x / M_TILES) * NT;

    const int wm = (wid & 1) * 32;   // warp M offset (2 warps in M)
    const int wn = (wid >> 1) * 32;  // warp N offset (4 warps in N)

    // --- load-index precompute ---
    // A: 64 rows x 128B; 512 chunk-tasks -> 2 per thread (rows tid>>3, +32)
    const int a_row = tid >> 3, a_col = tid & 7;
    // B: 128 rows x 128B; 1024 chunk-tasks -> 4 per thread (row tid>>1, 4 chunks)
    const int b_row = tid >> 1, b_col = (tid & 1) * 4;
    const char* a_src0 =
        (const char*)(g_x_half + (size_t)(m0 + a_row) * K_TOTAL) + a_col * 16;
    const char* b_src0 =
        (const char*)(g_w_half + (size_t)(n0 + b_row) * K_TOTAL) + b_col * 16;
    const uint32_t a_dst0 = SWZ((uint32_t)(a_row * 128 + a_col * 16));

    auto load_A = [&](int ls, uint32_t aB) {
        const char* src = a_src0 + (size_t)ls * (KC * 2);
        uint32_t dst = aB + a_dst0;
        cp16(dst, src);
        cp16(dst + 4096, src + (size_t)32 * K_TOTAL * 2);   // +32 rows
    };
    auto load_B = [&](int ls, uint32_t bB) {
        const char* src = b_src0 + (size_t)ls * (KC * 2);
        #pragma unroll
        for (int i = 0; i < 4; i++)
            cp16(bB + SWZ((uint32_t)(b_row * 128 + (b_col + i) * 16)), src + i * 16);
    };

    // --- prologue: fill STAGES-1 stages ---
    #pragma unroll
    for (int i = 0; i < STAGES - 1; i++) {
        uint32_t aB = sbase + (uint32_t)i * STAGE_BYTES;
        load_A(i, aB);
        load_B(i, aB + A_ST);
        asm volatile("cp.async.commit_group;" ::: "memory");
    }

    float acc[2][4][4];
    #pragma unroll
    for (int mi = 0; mi < 2; mi++)
        #pragma unroll
        for (int ni = 0; ni < 4; ni++)
            #pragma unroll
            for (int q = 0; q < 4; q++) acc[mi][ni][q] = 0.f;

    // --- mainloop ---
    #pragma unroll 1
    for (int kc = 0; kc < NKC; kc++) {
        const int ls = kc + STAGES - 1;

        asm volatile("cp.async.wait_group 2;" ::: "memory");
        __syncthreads();

        const uint32_t lsB = sbase + (uint32_t)(ls & (STAGES - 1)) * STAGE_BYTES;
        if (ls < NKC) {
            load_A(ls, lsB);
            load_B(ls, lsB + A_ST);
        }
        asm volatile("cp.async.commit_group;" ::: "memory");

        // compute stage kc
        {
            const uint32_t aB = sbase + (uint32_t)(kc & (STAGES - 1)) * STAGE_BYTES;
            const uint32_t bB = aB + A_ST;
            const int lrow = lane & 15;
            const int lk   = (lane >> 4) * 16;
            #pragma unroll
            for (int ks = 0; ks < 4; ks++) {
                const int kb = ks * 32 + lk;
                uint32_t a[2][4], b[2][4];
                #pragma unroll
                for (int mi = 0; mi < 2; mi++)
                    ldsm4(a[mi], aB + SWZ((uint32_t)((wm + mi * 16 + lrow) * 128 + kb)));
                #pragma unroll
                for (int nx = 0; nx < 2; nx++)
                    ldsm4(b[nx], bB + SWZ((uint32_t)((wn + nx * 16 + lrow) * 128 + kb)));
                #pragma unroll
                for (int mi = 0; mi < 2; mi++)
                    #pragma unroll
                    for (int ni = 0; ni < 4; ni++)
                        mma16816(acc[mi][ni], a[mi],
                                 b[ni >> 1][ni & 1], b[ni >> 1][(ni & 1) + 2]);
            }
        }
    }
    asm volatile("cp.async.wait_group 0;" ::: "memory");

    // --- epilogue: scale/bias in registers, direct f32 stores ---
    {
        const int r_base = m0 + wm + (lane >> 2);
        const int c_base = n0 + wn + (lane & 3) * 2;
        #pragma unroll
        for (int ni = 0; ni < 4; ni++) {
            const int c = c_base + ni * 8;
            const float s0 = __ldg(scale + c), s1 = __ldg(scale + c + 1);
            const float g0 = __ldg(bias + c),  g1 = __ldg(bias + c + 1);
            #pragma unroll
            for (int mi = 0; mi < 2; mi++) {
                const int r0 = r_base + mi * 16;
                float2 o;
                o.x = fmaf(acc[mi][ni][0], s0, g0);
                o.y = fmaf(acc[mi][ni][1], s1, g1);
                *reinterpret_cast<float2*>(out + (size_t)r0 * N_TOTAL + c) = o;
                o.x = fmaf(acc[mi][ni][2], s0, g0);
                o.y = fmaf(acc[mi][ni][3], s1, g1);
                *reinterpret_cast<float2*>(out + (size_t)(r0 + 8) * N_TOTAL + c) = o;
            }
        }
    }
}

// ---------------------------------------------------------------------------
// launch
// ---------------------------------------------------------------------------
extern "C" void kernel_launch(void* const* d_in, const int* in_sizes, int n_in,
                              void* d_out, int out_size) {
    (void)in_sizes; (void)n_in; (void)out_size;
    const float* x     = (const float*)d_in[0];
    const int*   w     = (const int*)d_in[1];     // weight_int8 materialized as int32
    const float* scale = (const float*)d_in[2];
    const float* bias  = (const float*)d_in[3];
    float* out = (float*)d_out;

    cudaFuncSetAttribute(cl_gemm_kernel,
                         cudaFuncAttributeMaxDynamicSharedMemorySize, SMEM_BYTES);

    convert_x_kernel<<<2048, 256>>>(x);
    convert_w_kernel<<<22016, 256>>>(w);
    cl_gemm_kernel<<<M_TILES * N_TILES, 256, SMEM_BYTES>>>(scale, bias, out);
}